// round 12
// baseline (speedup 1.0000x reference)
#include <cuda_runtime.h>
#include <cstdint>

static constexpr int NG      = 16;
static constexpr int NPG     = 4096;
static constexpr int NN      = NG * NPG;     // 65536 nodes
static constexpr int EE      = 1048576;      // edges
static constexpr int H       = 32;           // hidden
static constexpr int FC1_IN  = NPG * H;      // 131072
static constexpr int FC1_OUT = 256;
static constexpr int FC2_OUT = 64;
static constexpr int CHUNK   = 128;          // fc1 rows per block
static constexpr int FC1_BLOCKS = FC1_IN / CHUNK;   // 1024

static constexpr int NB = 888;               // persistent grid (build kernel)
static constexpr int NT = 256;
static constexpr int NWARP = NB * 8;

// agg kernel: 5 blocks/SM (reg headroom for unroll-8 gather)
static constexpr int NBA = 740;              // 148 x 5
static constexpr int NWARPA = NBA * 8;

// -------- scratch (device globals; no allocation allowed) --------
__device__ int   g_degi[NN];
__device__ int   g_cnt [NN];
__device__ int   g_off [NN];          // block-local exclusive offsets
__device__ int   g_bsum[256];         // per-256-node-chunk bases (after scan2)
__device__ float g_dinv[NN];
__device__ int   g_eidx[EE];          // CSR: src indices grouped by dst
__device__ float g_h0 [NN * H];
__device__ float g_h1 [NN * H];
__device__ float g_act[NN * H];       // final pre-activated features for fc1
__device__ float g_t1p[FC1_BLOCKS * NG * FC1_OUT];   // fc1 partials (16 MB)

// -------- software grid barriers (separate for each persistent kernel) ---
__device__ unsigned          g_bar_count;
__device__ volatile unsigned g_bar_gen;
__device__ unsigned          g_bar_count2;
__device__ volatile unsigned g_bar_gen2;

template<int N>
__device__ __forceinline__ void grid_sync_n(unsigned* cnt, volatile unsigned* gen_p) {
    __syncthreads();
    if (threadIdx.x == 0) {
        unsigned gen = *gen_p;
        __threadfence();                      // release
        unsigned old = atomicAdd(cnt, 1u);
        if (old == (unsigned)N - 1u) {
            *cnt = 0u;
            __threadfence();
            *gen_p = gen + 1u;                // release
        } else {
            while (*gen_p == gen) __nanosleep(64);
            __threadfence();                  // acquire
        }
    }
    __syncthreads();
}

// ---- packed f32x2 helpers (sm_103a) ----
__device__ __forceinline__ void fma2(unsigned long long& d,
                                     unsigned long long a,
                                     unsigned long long b) {
    asm("fma.rn.f32x2 %0, %1, %2, %0;" : "+l"(d) : "l"(a), "l"(b));
}
__device__ __forceinline__ unsigned long long pack2(float lo, float hi) {
    unsigned long long r;
    asm("mov.b64 %0, {%1, %2};" : "=l"(r) : "f"(lo), "f"(hi));
    return r;
}
__device__ __forceinline__ float unpack_sum(unsigned long long v) {
    float lo, hi;
    asm("mov.b64 {%0, %1}, %2;" : "=f"(lo), "=f"(hi) : "l"(v));
    return lo + hi;
}

// ==================== kernel 0: zero counters ====================
__global__ void zero_kernel() {
    int i = blockIdx.x * 256 + threadIdx.x;
    g_degi[i] = 0;
    g_cnt[i]  = 0;
}

// ==================== kernel 1: build (persistent) ====================
// P0 histogram -> P1/P2 scans -> P3 CSR fill + layer-1 transform
__global__ __launch_bounds__(NT, 6)
void build_kernel(const void* __restrict__ ei,
                  const float* __restrict__ x,
                  const float* __restrict__ W1) {
    __shared__ float sh[16 * 32];
    __shared__ int   shi[8];

    const int t = threadIdx.x, bid = blockIdx.x;
    const int lane = t & 31, wp = t >> 5;

    // dtype detect, per block (int64 buffers: odd 32-bit words all zero)
    const unsigned* w32 = (const unsigned*)ei;
    const int is64 = __syncthreads_and(w32[2 * t + 1] == 0u);

    // ---- P0: degree histogram ----
    if (is64) {
        const long long* p = (const long long*)ei + EE;
        for (int e = bid * NT + t; e < EE; e += NB * NT)
            atomicAdd(&g_degi[(int)__ldcs(&p[e])], 1);
    } else {
        const int* p = (const int*)ei + EE;
        for (int e = bid * NT + t; e < EE; e += NB * NT)
            atomicAdd(&g_degi[__ldcs(&p[e])], 1);
    }
    grid_sync_n<NB>(&g_bar_count, &g_bar_gen);

    // ---- P1: per-256-chunk exclusive scan; emits dinv + chunk totals ----
    if (bid < 256) {
        int i = bid * 256 + t;
        int v = g_degi[i];
        g_dinv[i] = rsqrtf((float)v + 1.0f);
        int s = v;
#pragma unroll
        for (int off = 1; off < 32; off <<= 1) {
            int xx = __shfl_up_sync(~0u, s, off);
            if (lane >= off) s += xx;
        }
        if (lane == 31) shi[wp] = s;
        __syncthreads();
        if (wp == 0) {
            int orig = (lane < 8) ? shi[lane] : 0;
            int ws = orig;
#pragma unroll
            for (int off = 1; off < 8; off <<= 1) {
                int xx = __shfl_up_sync(~0u, ws, off);
                if (lane >= off) ws += xx;
            }
            if (lane < 8) shi[lane] = ws - orig;
        }
        __syncthreads();
        g_off[i] = s - v + shi[wp];
        if (t == 255) g_bsum[bid] = s + shi[7];
    }
    grid_sync_n<NB>(&g_bar_count, &g_bar_gen);

    // ---- P2: exclusive scan of 256 chunk totals (block 0) ----
    if (bid == 0) {
        int v = g_bsum[t];
        int s = v;
#pragma unroll
        for (int off = 1; off < 32; off <<= 1) {
            int xx = __shfl_up_sync(~0u, s, off);
            if (lane >= off) s += xx;
        }
        if (lane == 31) shi[wp] = s;
        __syncthreads();
        if (wp == 0) {
            int orig = (lane < 8) ? shi[lane] : 0;
            int ws = orig;
#pragma unroll
            for (int off = 1; off < 8; off <<= 1) {
                int xx = __shfl_up_sync(~0u, ws, off);
                if (lane >= off) ws += xx;
            }
            if (lane < 8) shi[lane] = ws - orig;
        }
        __syncthreads();
        g_bsum[t] = s - v + shi[wp];
    }
    grid_sync_n<NB>(&g_bar_count, &g_bar_gen);

    // ---- P3: CSR fill + layer-1 transform ----
    for (int i = t; i < 16 * 32; i += NT) sh[i] = W1[i];
    __syncthreads();
    if (is64) {
        const long long* p = (const long long*)ei;
        for (int e = bid * NT + t; e < EE; e += NB * NT) {
            int s = (int)__ldcs(&p[e]);
            int d = (int)__ldcs(&p[EE + e]);
            g_eidx[g_off[d] + g_bsum[d >> 8] + atomicAdd(&g_cnt[d], 1)] = s;
        }
    } else {
        const int* p = (const int*)ei;
        for (int e = bid * NT + t; e < EE; e += NB * NT) {
            int s = __ldcs(&p[e]);
            int d = __ldcs(&p[EE + e]);
            g_eidx[g_off[d] + g_bsum[d >> 8] + atomicAdd(&g_cnt[d], 1)] = s;
        }
    }
    for (int n = bid * 8 + wp; n < NN; n += NWARP) {
        float a = (lane < 16) ? x[n * 16 + lane] : 0.0f;
        float o = 0.0f;
#pragma unroll
        for (int k = 0; k < 16; k++)
            o = fmaf(__shfl_sync(~0u, a, k), sh[k * 32 + lane], o);
        g_h0[n * 32 + lane] = o * g_dinv[n];
    }
}

// ==================== kernel 2: agg_all (persistent) ====================
// LAYER 0: in g_h0, out g_h1, fused matmul
// LAYER 1: in g_h1, out g_h0, fused matmul
// LAYER 2: in g_h0, out g_act, activation only (feeds fc1)
template<int LAYER>
__device__ __forceinline__ void agg_phase(const float* __restrict__ W,
                                          const float* __restrict__ b,
                                          float* sh, int bid, int t) {
    const float* hs_in = (LAYER == 1) ? g_h1 : g_h0;
    float* outp = (LAYER == 0) ? g_h1 : (LAYER == 1) ? g_h0 : g_act;
    if (LAYER < 2)
        for (int i = t; i < H * H; i += NT) sh[i] = W[i];
    __syncthreads();
    int lane = t & 31, wp = t >> 5;
    float bl = b[lane];
    const float* hp = hs_in + lane;
    for (int n = bid * 8 + wp; n < NN; n += NWARPA) {
        int start = g_off[n] + g_bsum[n >> 8];
        int end   = start + g_degi[n];
        float a0 = hs_in[n * H + lane];   // self-loop term
        float a1 = 0.f, a2 = 0.f, a3 = 0.f;
        float a4 = 0.f, a5 = 0.f, a6 = 0.f, a7 = 0.f;
        int e = start;
        while ((e & 3) && e < end)                    // align to int4
            a0 += hp[g_eidx[e++] * H];
        for (; e + 8 <= end; e += 8) {
            int4 i0 = *reinterpret_cast<const int4*>(&g_eidx[e]);
            int4 i1 = *reinterpret_cast<const int4*>(&g_eidx[e + 4]);
            a0 += hp[i0.x * H]; a1 += hp[i0.y * H];
            a2 += hp[i0.z * H]; a3 += hp[i0.w * H];
            a4 += hp[i1.x * H]; a5 += hp[i1.y * H];
            a6 += hp[i1.z * H]; a7 += hp[i1.w * H];
        }
        if (e + 4 <= end) {
            int4 i0 = *reinterpret_cast<const int4*>(&g_eidx[e]);
            a0 += hp[i0.x * H]; a1 += hp[i0.y * H];
            a2 += hp[i0.z * H]; a3 += hp[i0.w * H];
            e += 4;
        }
        for (; e < end; e++)
            a0 += hp[g_eidx[e] * H];
        float dv = g_dinv[n];
        float agg = ((a0 + a1) + (a2 + a3)) + ((a4 + a5) + (a6 + a7));
        float a = fmaxf(dv * agg + bl, 0.0f);
        if (LAYER == 2) { outp[n * H + lane] = a; continue; }
        float o = 0.0f;
#pragma unroll
        for (int k = 0; k < H; k++)
            o = fmaf(__shfl_sync(~0u, a, k), sh[k * H + lane], o);
        outp[n * H + lane] = o * dv;
    }
}

__global__ __launch_bounds__(NT, 5)
void agg_all_kernel(const float* __restrict__ W2, const float* __restrict__ b1,
                    const float* __restrict__ W3, const float* __restrict__ b2,
                    const float* __restrict__ b3) {
    __shared__ float sh[H * H];
    const int t = threadIdx.x, bid = blockIdx.x;
    agg_phase<0>(W2, b1, sh, bid, t);
    grid_sync_n<NBA>(&g_bar_count2, &g_bar_gen2);
    agg_phase<1>(W3, b2, sh, bid, t);
    grid_sync_n<NBA>(&g_bar_count2, &g_bar_gen2);
    agg_phase<2>(nullptr, b3, sh, bid, t);
}

// ==================== kernel 3: fc1 partials ====================
// 1024 blocks (CHUNK=128 rows each) — grid-limited occupancy fix;
// 8 weight loads in flight per thread (MLP 8).
__global__ void fc1_kernel(const float* __restrict__ fc1_w) {
    __shared__ float a_s[NG * CHUNK];            // 8 KB, [g][i]
    int t  = threadIdx.x;                         // output column 0..255
    int i0 = blockIdx.x * CHUNK;

    for (int idx = t; idx < NG * (CHUNK / 4); idx += 256) {
        int g  = idx / (CHUNK / 4);
        int i4 = idx & (CHUNK / 4 - 1);
        float4 v = *reinterpret_cast<const float4*>(g_act + g * FC1_IN + i0 + i4 * 4);
        *reinterpret_cast<float4*>(&a_s[g * CHUNK + i4 * 4]) = v;
    }
    __syncthreads();

    unsigned long long r2[NG];
#pragma unroll
    for (int g = 0; g < NG; g++) r2[g] = 0ull;

    for (int i = 0; i < CHUNK; i += 8) {
        int base = (i0 + i) * FC1_OUT + t;
        float w0 = __ldcs(&fc1_w[base]);
        float w1 = __ldcs(&fc1_w[base +     FC1_OUT]);
        float w2 = __ldcs(&fc1_w[base + 2 * FC1_OUT]);
        float w3 = __ldcs(&fc1_w[base + 3 * FC1_OUT]);
        float w4 = __ldcs(&fc1_w[base + 4 * FC1_OUT]);
        float w5 = __ldcs(&fc1_w[base + 5 * FC1_OUT]);
        float w6 = __ldcs(&fc1_w[base + 6 * FC1_OUT]);
        float w7 = __ldcs(&fc1_w[base + 7 * FC1_OUT]);
        unsigned long long wA = pack2(w0, w1);
        unsigned long long wB = pack2(w2, w3);
        unsigned long long wC = pack2(w4, w5);
        unsigned long long wD = pack2(w6, w7);
#pragma unroll
        for (int g = 0; g < NG; g++) {
            const unsigned long long* ap =
                reinterpret_cast<const unsigned long long*>(&a_s[g * CHUNK + i]);
            fma2(r2[g], ap[0], wA);
            fma2(r2[g], ap[1], wB);
            fma2(r2[g], ap[2], wC);
            fma2(r2[g], ap[3], wD);
        }
    }
    float* outp = g_t1p + blockIdx.x * (NG * FC1_OUT);
#pragma unroll
    for (int g = 0; g < NG; g++)
        outp[g * FC1_OUT + t] = unpack_sum(r2[g]);
}

// ==================== kernel 4: tail = reduce partials + fc2 ====================
// grid 16 (one block per graph) x 1024 threads.
__global__ void tail_kernel(const float* __restrict__ fc1_b,
                            const float* __restrict__ fc2_w,
                            const float* __restrict__ fc2_b,
                            float* __restrict__ out) {
    __shared__ float sp[1024];
    __shared__ float s[FC1_OUT];
    int g = blockIdx.x, t = threadIdx.x;
    int o = t & 255, q = t >> 8;                 // q in 0..3: slice of partials

    const float* p = g_t1p + g * FC1_OUT + o;
    float acc = 0.0f;
    const int SLICE = FC1_BLOCKS / 4;            // 256
#pragma unroll 8
    for (int i = 0; i < SLICE; i++)
        acc += p[(q * SLICE + i) * (NG * FC1_OUT)];
    sp[q * 256 + o] = acc;
    __syncthreads();
    if (t < FC1_OUT)
        s[t] = fmaxf(sp[t] + sp[256 + t] + sp[512 + t] + sp[768 + t] + fc1_b[t], 0.0f);
    __syncthreads();

    // fc2: 64 outputs x 16 threads each (16 k per thread), shfl reduce
    int oo = t >> 4, qq = t & 15;
    float a2 = 0.0f;
#pragma unroll
    for (int k = qq * 16; k < qq * 16 + 16; k++)
        a2 = fmaf(s[k], fc2_w[k * FC2_OUT + oo], a2);
    a2 += __shfl_down_sync(~0u, a2, 8, 16);
    a2 += __shfl_down_sync(~0u, a2, 4, 16);
    a2 += __shfl_down_sync(~0u, a2, 2, 16);
    a2 += __shfl_down_sync(~0u, a2, 1, 16);
    if (qq == 0)
        out[g * FC2_OUT + oo] = a2 + fc2_b[oo];
}

extern "C" void kernel_launch(void* const* d_in, const int* in_sizes, int n_in,
                              void* d_out, int out_size) {
    zero_kernel<<<NN / 256, 256>>>();
    build_kernel<<<NB, NT>>>(d_in[1], (const float*)d_in[0], (const float*)d_in[2]);
    agg_all_kernel<<<NBA, NT>>>((const float*)d_in[4], (const float*)d_in[3],
                                (const float*)d_in[6], (const float*)d_in[5],
                                (const float*)d_in[7]);
    fc1_kernel<<<FC1_BLOCKS, 256>>>((const float*)d_in[8]);
    tail_kernel<<<NG, 1024>>>((const float*)d_in[9],
                              (const float*)d_in[10],
                              (const float*)d_in[11],
                              (float*)d_out);
}

// round 13
// speedup vs baseline: 1.0097x; 1.0097x over previous
#include <cuda_runtime.h>
#include <cstdint>

static constexpr int NG      = 16;
static constexpr int NPG     = 4096;
static constexpr int NN      = NG * NPG;     // 65536 nodes
static constexpr int EE      = 1048576;      // edges
static constexpr int H       = 32;           // hidden
static constexpr int FC1_IN  = NPG * H;      // 131072
static constexpr int FC1_OUT = 256;
static constexpr int FC2_OUT = 64;
static constexpr int CHUNK   = 256;          // fc1 rows per block
static constexpr int FC1_BLOCKS = FC1_IN / CHUNK;   // 512
static constexpr int NGROUPS = CHUNK / 8;    // 32 pipeline groups per block

static constexpr int NB = 888;               // persistent grid (build kernel)
static constexpr int NT = 256;
static constexpr int NWARP = NB * 8;

// agg kernel: 5 blocks/SM
static constexpr int NBA = 740;              // 148 x 5
static constexpr int NWARPA = NBA * 8;

// -------- scratch (device globals; no allocation allowed) --------
__device__ int   g_degi[NN];
__device__ int   g_cnt [NN];
__device__ int   g_off [NN];          // block-local exclusive offsets
__device__ int   g_bsum[256];         // per-256-node-chunk bases (after scan2)
__device__ float g_dinv[NN];
__device__ int   g_eidx[EE];          // CSR: src indices grouped by dst
__device__ float g_h0 [NN * H];
__device__ float g_h1 [NN * H];
__device__ float g_act[NN * H];       // final pre-activated features for fc1
__device__ float g_t1p[FC1_BLOCKS * NG * FC1_OUT];   // fc1 partials (8 MB)

// -------- software grid barriers (separate for each persistent kernel) ---
__device__ unsigned          g_bar_count;
__device__ volatile unsigned g_bar_gen;
__device__ unsigned          g_bar_count2;
__device__ volatile unsigned g_bar_gen2;

template<int N>
__device__ __forceinline__ void grid_sync_n(unsigned* cnt, volatile unsigned* gen_p) {
    __syncthreads();
    if (threadIdx.x == 0) {
        unsigned gen = *gen_p;
        __threadfence();                      // release
        unsigned old = atomicAdd(cnt, 1u);
        if (old == (unsigned)N - 1u) {
            *cnt = 0u;
            __threadfence();
            *gen_p = gen + 1u;                // release
        } else {
            while (*gen_p == gen) __nanosleep(64);
            __threadfence();                  // acquire
        }
    }
    __syncthreads();
}

// ---- packed f32x2 helpers (sm_103a) ----
__device__ __forceinline__ void fma2(unsigned long long& d,
                                     unsigned long long a,
                                     unsigned long long b) {
    asm("fma.rn.f32x2 %0, %1, %2, %0;" : "+l"(d) : "l"(a), "l"(b));
}
__device__ __forceinline__ unsigned long long pack2(float lo, float hi) {
    unsigned long long r;
    asm("mov.b64 %0, {%1, %2};" : "=l"(r) : "f"(lo), "f"(hi));
    return r;
}
__device__ __forceinline__ float unpack_sum(unsigned long long v) {
    float lo, hi;
    asm("mov.b64 {%0, %1}, %2;" : "=f"(lo), "=f"(hi) : "l"(v));
    return lo + hi;
}
__device__ __forceinline__ void cpasync16(uint32_t dst_smem, const void* src) {
    asm volatile("cp.async.cg.shared.global [%0], [%1], 16;"
                 :: "r"(dst_smem), "l"(src));
}

// ==================== kernel 0: zero counters ====================
__global__ void zero_kernel() {
    int i = blockIdx.x * 256 + threadIdx.x;
    g_degi[i] = 0;
    g_cnt[i]  = 0;
}

// ==================== kernel 1: build (persistent) ====================
__global__ __launch_bounds__(NT, 6)
void build_kernel(const void* __restrict__ ei,
                  const float* __restrict__ x,
                  const float* __restrict__ W1) {
    __shared__ float sh[16 * 32];
    __shared__ int   shi[8];

    const int t = threadIdx.x, bid = blockIdx.x;
    const int lane = t & 31, wp = t >> 5;

    // dtype detect, per block (int64 buffers: odd 32-bit words all zero)
    const unsigned* w32 = (const unsigned*)ei;
    const int is64 = __syncthreads_and(w32[2 * t + 1] == 0u);

    // ---- P0: degree histogram ----
    if (is64) {
        const long long* p = (const long long*)ei + EE;
        for (int e = bid * NT + t; e < EE; e += NB * NT)
            atomicAdd(&g_degi[(int)__ldcs(&p[e])], 1);
    } else {
        const int* p = (const int*)ei + EE;
        for (int e = bid * NT + t; e < EE; e += NB * NT)
            atomicAdd(&g_degi[__ldcs(&p[e])], 1);
    }
    grid_sync_n<NB>(&g_bar_count, &g_bar_gen);

    // ---- P1: per-256-chunk exclusive scan; emits dinv + chunk totals ----
    if (bid < 256) {
        int i = bid * 256 + t;
        int v = g_degi[i];
        g_dinv[i] = rsqrtf((float)v + 1.0f);
        int s = v;
#pragma unroll
        for (int off = 1; off < 32; off <<= 1) {
            int xx = __shfl_up_sync(~0u, s, off);
            if (lane >= off) s += xx;
        }
        if (lane == 31) shi[wp] = s;
        __syncthreads();
        if (wp == 0) {
            int orig = (lane < 8) ? shi[lane] : 0;
            int ws = orig;
#pragma unroll
            for (int off = 1; off < 8; off <<= 1) {
                int xx = __shfl_up_sync(~0u, ws, off);
                if (lane >= off) ws += xx;
            }
            if (lane < 8) shi[lane] = ws - orig;
        }
        __syncthreads();
        g_off[i] = s - v + shi[wp];
        if (t == 255) g_bsum[bid] = s + shi[7];
    }
    grid_sync_n<NB>(&g_bar_count, &g_bar_gen);

    // ---- P2: exclusive scan of 256 chunk totals (block 0) ----
    if (bid == 0) {
        int v = g_bsum[t];
        int s = v;
#pragma unroll
        for (int off = 1; off < 32; off <<= 1) {
            int xx = __shfl_up_sync(~0u, s, off);
            if (lane >= off) s += xx;
        }
        if (lane == 31) shi[wp] = s;
        __syncthreads();
        if (wp == 0) {
            int orig = (lane < 8) ? shi[lane] : 0;
            int ws = orig;
#pragma unroll
            for (int off = 1; off < 8; off <<= 1) {
                int xx = __shfl_up_sync(~0u, ws, off);
                if (lane >= off) ws += xx;
            }
            if (lane < 8) shi[lane] = ws - orig;
        }
        __syncthreads();
        g_bsum[t] = s - v + shi[wp];
    }
    grid_sync_n<NB>(&g_bar_count, &g_bar_gen);

    // ---- P3: CSR fill + layer-1 transform ----
    for (int i = t; i < 16 * 32; i += NT) sh[i] = W1[i];
    __syncthreads();
    if (is64) {
        const long long* p = (const long long*)ei;
        for (int e = bid * NT + t; e < EE; e += NB * NT) {
            int s = (int)__ldcs(&p[e]);
            int d = (int)__ldcs(&p[EE + e]);
            g_eidx[g_off[d] + g_bsum[d >> 8] + atomicAdd(&g_cnt[d], 1)] = s;
        }
    } else {
        const int* p = (const int*)ei;
        for (int e = bid * NT + t; e < EE; e += NB * NT) {
            int s = __ldcs(&p[e]);
            int d = __ldcs(&p[EE + e]);
            g_eidx[g_off[d] + g_bsum[d >> 8] + atomicAdd(&g_cnt[d], 1)] = s;
        }
    }
    for (int n = bid * 8 + wp; n < NN; n += NWARP) {
        float a = (lane < 16) ? x[n * 16 + lane] : 0.0f;
        float o = 0.0f;
#pragma unroll
        for (int k = 0; k < 16; k++)
            o = fmaf(__shfl_sync(~0u, a, k), sh[k * 32 + lane], o);
        g_h0[n * 32 + lane] = o * g_dinv[n];
    }
}

// ==================== kernel 2: agg_all (persistent) ====================
template<int LAYER>
__device__ __forceinline__ void agg_phase(const float* __restrict__ W,
                                          const float* __restrict__ b,
                                          float* sh, int bid, int t) {
    const float* hs_in = (LAYER == 1) ? g_h1 : g_h0;
    float* outp = (LAYER == 0) ? g_h1 : (LAYER == 1) ? g_h0 : g_act;
    if (LAYER < 2)
        for (int i = t; i < H * H; i += NT) sh[i] = W[i];
    __syncthreads();
    int lane = t & 31, wp = t >> 5;
    float bl = b[lane];
    const float* hp = hs_in + lane;
    for (int n = bid * 8 + wp; n < NN; n += NWARPA) {
        int start = g_off[n] + g_bsum[n >> 8];
        int end   = start + g_degi[n];
        float a0 = hs_in[n * H + lane];   // self-loop term
        float a1 = 0.f, a2 = 0.f, a3 = 0.f;
        float a4 = 0.f, a5 = 0.f, a6 = 0.f, a7 = 0.f;
        int e = start;
        while ((e & 3) && e < end)                    // align to int4
            a0 += hp[g_eidx[e++] * H];
        for (; e + 8 <= end; e += 8) {
            int4 i0 = *reinterpret_cast<const int4*>(&g_eidx[e]);
            int4 i1 = *reinterpret_cast<const int4*>(&g_eidx[e + 4]);
            a0 += hp[i0.x * H]; a1 += hp[i0.y * H];
            a2 += hp[i0.z * H]; a3 += hp[i0.w * H];
            a4 += hp[i1.x * H]; a5 += hp[i1.y * H];
            a6 += hp[i1.z * H]; a7 += hp[i1.w * H];
        }
        if (e + 4 <= end) {
            int4 i0 = *reinterpret_cast<const int4*>(&g_eidx[e]);
            a0 += hp[i0.x * H]; a1 += hp[i0.y * H];
            a2 += hp[i0.z * H]; a3 += hp[i0.w * H];
            e += 4;
        }
        for (; e < end; e++)
            a0 += hp[g_eidx[e] * H];
        float dv = g_dinv[n];
        float agg = ((a0 + a1) + (a2 + a3)) + ((a4 + a5) + (a6 + a7));
        float a = fmaxf(dv * agg + bl, 0.0f);
        if (LAYER == 2) { outp[n * H + lane] = a; continue; }
        float o = 0.0f;
#pragma unroll
        for (int k = 0; k < H; k++)
            o = fmaf(__shfl_sync(~0u, a, k), sh[k * H + lane], o);
        outp[n * H + lane] = o * dv;
    }
}

__global__ __launch_bounds__(NT, 5)
void agg_all_kernel(const float* __restrict__ W2, const float* __restrict__ b1,
                    const float* __restrict__ W3, const float* __restrict__ b2,
                    const float* __restrict__ b3) {
    __shared__ float sh[H * H];
    const int t = threadIdx.x, bid = blockIdx.x;
    agg_phase<0>(W2, b1, sh, bid, t);
    grid_sync_n<NBA>(&g_bar_count2, &g_bar_gen2);
    agg_phase<1>(W3, b2, sh, bid, t);
    grid_sync_n<NBA>(&g_bar_count2, &g_bar_gen2);
    agg_phase<2>(nullptr, b3, sh, bid, t);
}

// ==================== kernel 3: fc1 partials (cp.async pipelined) ========
// 512 blocks, CHUNK=256 rows each; weights streamed via 4-stage cp.async
// pipeline (8 rows = 8 KB per stage) -> in-flight bytes independent of regs.
__global__ __launch_bounds__(256, 4)
void fc1_kernel(const float* __restrict__ fc1_w) {
    __shared__ float a_s[NG * CHUNK];                 // 16 KB, [g][i]
    __shared__ __align__(16) float w_s[4 * 8 * FC1_OUT];   // 32 KB, 4 stages
    int t  = threadIdx.x;                              // output column 0..255
    int i0 = blockIdx.x * CHUNK;

    uint32_t w_base = (uint32_t)__cvta_generic_to_shared(w_s);

    // prologue: prefetch weight groups 0..2
#pragma unroll
    for (int grp = 0; grp < 3; grp++) {
        const float* src = fc1_w + (long)(i0 + grp * 8) * FC1_OUT;
        uint32_t dst = w_base + grp * 8192;
        for (int k = t; k < 512; k += 256)
            cpasync16(dst + k * 16, src + k * 4);
        asm volatile("cp.async.commit_group;" ::: "memory");
    }

    // load activations (16 graphs x CHUNK) as float4
    for (int idx = t; idx < NG * (CHUNK / 4); idx += 256) {
        int g  = idx / (CHUNK / 4);
        int i4 = idx & (CHUNK / 4 - 1);
        float4 v = *reinterpret_cast<const float4*>(g_act + g * FC1_IN + i0 + i4 * 4);
        *reinterpret_cast<float4*>(&a_s[g * CHUNK + i4 * 4]) = v;
    }

    unsigned long long r2[NG];
#pragma unroll
    for (int g = 0; g < NG; g++) r2[g] = 0ull;

    for (int grp = 0; grp < NGROUPS; grp++) {
        if (grp < NGROUPS - 3)
            asm volatile("cp.async.wait_group 2;" ::: "memory");
        else
            asm volatile("cp.async.wait_group 0;" ::: "memory");
        __syncthreads();                 // group grp visible to all threads
        if (grp + 3 < NGROUPS) {         // refill slot (grp+3)&3 (safe: its
            const float* src = fc1_w + (long)(i0 + (grp + 3) * 8) * FC1_OUT;   // prior user, group grp-1, was
            uint32_t dst = w_base + ((grp + 3) & 3) * 8192;                    // consumed before this sync)
            for (int k = t; k < 512; k += 256)
                cpasync16(dst + k * 16, src + k * 4);
            asm volatile("cp.async.commit_group;" ::: "memory");
        }
        const float* wrow = w_s + (grp & 3) * 2048;
#pragma unroll
        for (int pr = 0; pr < 4; pr++) {
            float wlo = wrow[(pr * 2)     * FC1_OUT + t];
            float whi = wrow[(pr * 2 + 1) * FC1_OUT + t];
            unsigned long long wp = pack2(wlo, whi);
            int ib = grp * 8 + pr * 2;
#pragma unroll
            for (int g = 0; g < NG; g++)
                fma2(r2[g],
                     *reinterpret_cast<const unsigned long long*>(&a_s[g * CHUNK + ib]),
                     wp);
        }
    }
    float* outp = g_t1p + blockIdx.x * (NG * FC1_OUT);
#pragma unroll
    for (int g = 0; g < NG; g++)
        outp[g * FC1_OUT + t] = unpack_sum(r2[g]);
}

// ==================== kernel 4: tail = reduce partials + fc2 ====================
// grid 16 (one block per graph) x 1024 threads.
__global__ void tail_kernel(const float* __restrict__ fc1_b,
                            const float* __restrict__ fc2_w,
                            const float* __restrict__ fc2_b,
                            float* __restrict__ out) {
    __shared__ float sp[1024];
    __shared__ float s[FC1_OUT];
    int g = blockIdx.x, t = threadIdx.x;
    int o = t & 255, q = t >> 8;                 // q in 0..3: slice of partials

    const float* p = g_t1p + g * FC1_OUT + o;
    float acc = 0.0f;
    const int SLICE = FC1_BLOCKS / 4;            // 128
#pragma unroll 8
    for (int i = 0; i < SLICE; i++)
        acc += p[(q * SLICE + i) * (NG * FC1_OUT)];
    sp[q * 256 + o] = acc;
    __syncthreads();
    if (t < FC1_OUT)
        s[t] = fmaxf(sp[t] + sp[256 + t] + sp[512 + t] + sp[768 + t] + fc1_b[t], 0.0f);
    __syncthreads();

    // fc2: 64 outputs x 16 threads each (16 k per thread), shfl reduce
    int oo = t >> 4, qq = t & 15;
    float a2 = 0.0f;
#pragma unroll
    for (int k = qq * 16; k < qq * 16 + 16; k++)
        a2 = fmaf(s[k], fc2_w[k * FC2_OUT + oo], a2);
    a2 += __shfl_down_sync(~0u, a2, 8, 16);
    a2 += __shfl_down_sync(~0u, a2, 4, 16);
    a2 += __shfl_down_sync(~0u, a2, 2, 16);
    a2 += __shfl_down_sync(~0u, a2, 1, 16);
    if (qq == 0)
        out[g * FC2_OUT + oo] = a2 + fc2_b[oo];
}

extern "C" void kernel_launch(void* const* d_in, const int* in_sizes, int n_in,
                              void* d_out, int out_size) {
    zero_kernel<<<NN / 256, 256>>>();
    build_kernel<<<NB, NT>>>(d_in[1], (const float*)d_in[0], (const float*)d_in[2]);
    agg_all_kernel<<<NBA, NT>>>((const float*)d_in[4], (const float*)d_in[3],
                                (const float*)d_in[6], (const float*)d_in[5],
                                (const float*)d_in[7]);
    fc1_kernel<<<FC1_BLOCKS, 256>>>((const float*)d_in[8]);
    tail_kernel<<<NG, 1024>>>((const float*)d_in[9],
                              (const float*)d_in[10],
                              (const float*)d_in[11],
                              (float*)d_out);
}

// round 14
// speedup vs baseline: 1.0422x; 1.0322x over previous
#include <cuda_runtime.h>
#include <cstdint>

static constexpr int NG      = 16;
static constexpr int NPG     = 4096;
static constexpr int NN      = NG * NPG;     // 65536 nodes
static constexpr int EE      = 1048576;      // edges
static constexpr int H       = 32;           // hidden
static constexpr int FC1_IN  = NPG * H;      // 131072
static constexpr int FC1_OUT = 256;
static constexpr int FC2_OUT = 64;
static constexpr int CHUNK   = 256;          // fc1 rows per block
static constexpr int FC1_BLOCKS = FC1_IN / CHUNK;   // 512
static constexpr int NGROUPS = CHUNK / 8;    // 32 pipeline groups per block

static constexpr int NB = 888;               // persistent grid (build kernel)
static constexpr int NT = 256;
static constexpr int NWARP = NB * 8;

// agg kernel: 5 blocks/SM
static constexpr int NBA = 740;              // 148 x 5
static constexpr int NWARPA = NBA * 8;

// -------- scratch (device globals; no allocation allowed) --------
__device__ int   g_degi[NN];
__device__ int   g_cnt [NN];
__device__ int   g_off [NN];          // block-local exclusive offsets
__device__ int   g_bsum[256];         // per-256-node-chunk bases (after scan2)
__device__ float g_dinv[NN];
__device__ int   g_eidx[EE];          // CSR: src indices grouped by dst
__device__ float g_h0 [NN * H];
__device__ float g_h1 [NN * H];
__device__ float g_act[NN * H];       // final pre-activated features for fc1
__device__ float g_t1p[FC1_BLOCKS * NG * FC1_OUT];   // fc1 partials (8 MB)

// -------- software grid barriers (separate for each persistent kernel) ---
__device__ unsigned          g_bar_count;
__device__ volatile unsigned g_bar_gen;
__device__ unsigned          g_bar_count2;
__device__ volatile unsigned g_bar_gen2;

template<int N>
__device__ __forceinline__ void grid_sync_n(unsigned* cnt, volatile unsigned* gen_p) {
    __syncthreads();
    if (threadIdx.x == 0) {
        unsigned gen = *gen_p;
        __threadfence();                      // release
        unsigned old = atomicAdd(cnt, 1u);
        if (old == (unsigned)N - 1u) {
            *cnt = 0u;
            __threadfence();
            *gen_p = gen + 1u;                // release
        } else {
            while (*gen_p == gen) __nanosleep(64);
            __threadfence();                  // acquire
        }
    }
    __syncthreads();
}

// ---- packed f32x2 helpers (sm_103a) ----
__device__ __forceinline__ void fma2(unsigned long long& d,
                                     unsigned long long a,
                                     unsigned long long b) {
    asm("fma.rn.f32x2 %0, %1, %2, %0;" : "+l"(d) : "l"(a), "l"(b));
}
__device__ __forceinline__ unsigned long long pack2(float lo, float hi) {
    unsigned long long r;
    asm("mov.b64 %0, {%1, %2};" : "=l"(r) : "f"(lo), "f"(hi));
    return r;
}
__device__ __forceinline__ float unpack_sum(unsigned long long v) {
    float lo, hi;
    asm("mov.b64 {%0, %1}, %2;" : "=f"(lo), "=f"(hi) : "l"(v));
    return lo + hi;
}

// ---- mbarrier + bulk-copy helpers ----
__device__ __forceinline__ void mbar_init(uint32_t mbar, int count) {
    asm volatile("mbarrier.init.shared.b64 [%0], %1;" :: "r"(mbar), "r"(count) : "memory");
}
__device__ __forceinline__ void mbar_expect_tx(uint32_t mbar, int bytes) {
    asm volatile("mbarrier.arrive.expect_tx.shared.b64 _, [%0], %1;"
                 :: "r"(mbar), "r"(bytes) : "memory");
}
__device__ __forceinline__ void bulk_g2s(uint32_t dst, const void* src,
                                         int bytes, uint32_t mbar) {
    asm volatile("cp.async.bulk.shared::cta.global.mbarrier::complete_tx::bytes "
                 "[%0], [%1], %2, [%3];"
                 :: "r"(dst), "l"(src), "r"(bytes), "r"(mbar) : "memory");
}
__device__ __forceinline__ void mbar_wait(uint32_t mbar, int parity) {
    asm volatile(
        "{\n\t.reg .pred P1;\n\t"
        "WAIT_LOOP_%=:\n\t"
        "mbarrier.try_wait.parity.shared.b64 P1, [%0], %1;\n\t"
        "@P1 bra.uni WAIT_DONE_%=;\n\t"
        "bra.uni WAIT_LOOP_%=;\n\t"
        "WAIT_DONE_%=:\n\t}"
        :: "r"(mbar), "r"(parity) : "memory");
}

// ==================== kernel 0: zero counters ====================
__global__ void zero_kernel() {
    int i = blockIdx.x * 256 + threadIdx.x;
    g_degi[i] = 0;
    g_cnt[i]  = 0;
}

// ==================== kernel 1: build (persistent) ====================
__global__ __launch_bounds__(NT, 6)
void build_kernel(const void* __restrict__ ei,
                  const float* __restrict__ x,
                  const float* __restrict__ W1) {
    __shared__ float sh[16 * 32];
    __shared__ int   shi[8];

    const int t = threadIdx.x, bid = blockIdx.x;
    const int lane = t & 31, wp = t >> 5;

    // dtype detect, per block (int64 buffers: odd 32-bit words all zero)
    const unsigned* w32 = (const unsigned*)ei;
    const int is64 = __syncthreads_and(w32[2 * t + 1] == 0u);

    // ---- P0: degree histogram ----
    if (is64) {
        const long long* p = (const long long*)ei + EE;
        for (int e = bid * NT + t; e < EE; e += NB * NT)
            atomicAdd(&g_degi[(int)__ldcs(&p[e])], 1);
    } else {
        const int* p = (const int*)ei + EE;
        for (int e = bid * NT + t; e < EE; e += NB * NT)
            atomicAdd(&g_degi[__ldcs(&p[e])], 1);
    }
    grid_sync_n<NB>(&g_bar_count, &g_bar_gen);

    // ---- P1: per-256-chunk exclusive scan; emits dinv + chunk totals ----
    if (bid < 256) {
        int i = bid * 256 + t;
        int v = g_degi[i];
        g_dinv[i] = rsqrtf((float)v + 1.0f);
        int s = v;
#pragma unroll
        for (int off = 1; off < 32; off <<= 1) {
            int xx = __shfl_up_sync(~0u, s, off);
            if (lane >= off) s += xx;
        }
        if (lane == 31) shi[wp] = s;
        __syncthreads();
        if (wp == 0) {
            int orig = (lane < 8) ? shi[lane] : 0;
            int ws = orig;
#pragma unroll
            for (int off = 1; off < 8; off <<= 1) {
                int xx = __shfl_up_sync(~0u, ws, off);
                if (lane >= off) ws += xx;
            }
            if (lane < 8) shi[lane] = ws - orig;
        }
        __syncthreads();
        g_off[i] = s - v + shi[wp];
        if (t == 255) g_bsum[bid] = s + shi[7];
    }
    grid_sync_n<NB>(&g_bar_count, &g_bar_gen);

    // ---- P2: exclusive scan of 256 chunk totals (block 0) ----
    if (bid == 0) {
        int v = g_bsum[t];
        int s = v;
#pragma unroll
        for (int off = 1; off < 32; off <<= 1) {
            int xx = __shfl_up_sync(~0u, s, off);
            if (lane >= off) s += xx;
        }
        if (lane == 31) shi[wp] = s;
        __syncthreads();
        if (wp == 0) {
            int orig = (lane < 8) ? shi[lane] : 0;
            int ws = orig;
#pragma unroll
            for (int off = 1; off < 8; off <<= 1) {
                int xx = __shfl_up_sync(~0u, ws, off);
                if (lane >= off) ws += xx;
            }
            if (lane < 8) shi[lane] = ws - orig;
        }
        __syncthreads();
        g_bsum[t] = s - v + shi[wp];
    }
    grid_sync_n<NB>(&g_bar_count, &g_bar_gen);

    // ---- P3: CSR fill + layer-1 transform ----
    for (int i = t; i < 16 * 32; i += NT) sh[i] = W1[i];
    __syncthreads();
    if (is64) {
        const long long* p = (const long long*)ei;
        for (int e = bid * NT + t; e < EE; e += NB * NT) {
            int s = (int)__ldcs(&p[e]);
            int d = (int)__ldcs(&p[EE + e]);
            g_eidx[g_off[d] + g_bsum[d >> 8] + atomicAdd(&g_cnt[d], 1)] = s;
        }
    } else {
        const int* p = (const int*)ei;
        for (int e = bid * NT + t; e < EE; e += NB * NT) {
            int s = __ldcs(&p[e]);
            int d = __ldcs(&p[EE + e]);
            g_eidx[g_off[d] + g_bsum[d >> 8] + atomicAdd(&g_cnt[d], 1)] = s;
        }
    }
    for (int n = bid * 8 + wp; n < NN; n += NWARP) {
        float a = (lane < 16) ? x[n * 16 + lane] : 0.0f;
        float o = 0.0f;
#pragma unroll
        for (int k = 0; k < 16; k++)
            o = fmaf(__shfl_sync(~0u, a, k), sh[k * 32 + lane], o);
        g_h0[n * 32 + lane] = o * g_dinv[n];
    }
}

// ==================== kernel 2: agg_all (persistent) ====================
template<int LAYER>
__device__ __forceinline__ void agg_phase(const float* __restrict__ W,
                                          const float* __restrict__ b,
                                          float* sh, int bid, int t) {
    const float* hs_in = (LAYER == 1) ? g_h1 : g_h0;
    float* outp = (LAYER == 0) ? g_h1 : (LAYER == 1) ? g_h0 : g_act;
    if (LAYER < 2)
        for (int i = t; i < H * H; i += NT) sh[i] = W[i];
    __syncthreads();
    int lane = t & 31, wp = t >> 5;
    float bl = b[lane];
    const float* hp = hs_in + lane;
    for (int n = bid * 8 + wp; n < NN; n += NWARPA) {
        int start = g_off[n] + g_bsum[n >> 8];
        int end   = start + g_degi[n];
        float a0 = hs_in[n * H + lane];   // self-loop term
        float a1 = 0.f, a2 = 0.f, a3 = 0.f;
        float a4 = 0.f, a5 = 0.f, a6 = 0.f, a7 = 0.f;
        int e = start;
        while ((e & 3) && e < end)                    // align to int4
            a0 += hp[g_eidx[e++] * H];
        for (; e + 8 <= end; e += 8) {
            int4 i0 = *reinterpret_cast<const int4*>(&g_eidx[e]);
            int4 i1 = *reinterpret_cast<const int4*>(&g_eidx[e + 4]);
            a0 += hp[i0.x * H]; a1 += hp[i0.y * H];
            a2 += hp[i0.z * H]; a3 += hp[i0.w * H];
            a4 += hp[i1.x * H]; a5 += hp[i1.y * H];
            a6 += hp[i1.z * H]; a7 += hp[i1.w * H];
        }
        if (e + 4 <= end) {
            int4 i0 = *reinterpret_cast<const int4*>(&g_eidx[e]);
            a0 += hp[i0.x * H]; a1 += hp[i0.y * H];
            a2 += hp[i0.z * H]; a3 += hp[i0.w * H];
            e += 4;
        }
        for (; e < end; e++)
            a0 += hp[g_eidx[e] * H];
        float dv = g_dinv[n];
        float agg = ((a0 + a1) + (a2 + a3)) + ((a4 + a5) + (a6 + a7));
        float a = fmaxf(dv * agg + bl, 0.0f);
        if (LAYER == 2) { outp[n * H + lane] = a; continue; }
        float o = 0.0f;
#pragma unroll
        for (int k = 0; k < H; k++)
            o = fmaf(__shfl_sync(~0u, a, k), sh[k * H + lane], o);
        outp[n * H + lane] = o * dv;
    }
}

__global__ __launch_bounds__(NT, 5)
void agg_all_kernel(const float* __restrict__ W2, const float* __restrict__ b1,
                    const float* __restrict__ W3, const float* __restrict__ b2,
                    const float* __restrict__ b3) {
    __shared__ float sh[H * H];
    const int t = threadIdx.x, bid = blockIdx.x;
    agg_phase<0>(W2, b1, sh, bid, t);
    grid_sync_n<NBA>(&g_bar_count2, &g_bar_gen2);
    agg_phase<1>(W3, b2, sh, bid, t);
    grid_sync_n<NBA>(&g_bar_count2, &g_bar_gen2);
    agg_phase<2>(nullptr, b3, sh, bid, t);
}

// ==================== kernel 3: fc1 partials (cp.async.bulk pipelined) ===
// Weight stream via single-instruction 8 KB bulk copies (off the LSU issue
// path — LDG/LDGSTS issue floors were the 55 us wall). 4 stages, mbarrier
// completion, parity (grp>>2)&1. Activations read as LDS.128.
__global__ __launch_bounds__(256, 4)
void fc1_kernel(const float* __restrict__ fc1_w) {
    __shared__ __align__(16)  float a_s[NG * CHUNK];           // 16 KB
    __shared__ __align__(128) float w_s[4 * 8 * FC1_OUT];      // 32 KB
    __shared__ __align__(8)   unsigned long long mbar[4];
    int t  = threadIdx.x;                              // output column 0..255
    int i0 = blockIdx.x * CHUNK;

    uint32_t w_base = (uint32_t)__cvta_generic_to_shared(w_s);
    uint32_t mb_base = (uint32_t)__cvta_generic_to_shared(mbar);

    if (t == 0) {
#pragma unroll
        for (int s = 0; s < 4; s++) mbar_init(mb_base + s * 8, 1);
    }
    __syncthreads();

    // prologue: stage groups 0..2
    if (t == 0) {
#pragma unroll
        for (int grp = 0; grp < 3; grp++) {
            mbar_expect_tx(mb_base + grp * 8, 8192);
            bulk_g2s(w_base + grp * 8192,
                     fc1_w + (long)(i0 + grp * 8) * FC1_OUT, 8192,
                     mb_base + grp * 8);
        }
    }

    // load activations (16 graphs x CHUNK) as float4
    for (int idx = t; idx < NG * (CHUNK / 4); idx += 256) {
        int g  = idx / (CHUNK / 4);
        int i4 = idx & (CHUNK / 4 - 1);
        float4 v = *reinterpret_cast<const float4*>(g_act + g * FC1_IN + i0 + i4 * 4);
        *reinterpret_cast<float4*>(&a_s[g * CHUNK + i4 * 4]) = v;
    }

    unsigned long long r2[NG];
#pragma unroll
    for (int g = 0; g < NG; g++) r2[g] = 0ull;

    const float4* a4 = reinterpret_cast<const float4*>(a_s);

    for (int grp = 0; grp < NGROUPS; grp++) {
        int slot = grp & 3;
        mbar_wait(mb_base + slot * 8, (grp >> 2) & 1);
        __syncthreads();   // all threads past group grp-1's compute -> the
                           // refill target slot (grp+3)&3 == (grp-1)&3 is free
        if (t == 0 && grp + 3 < NGROUPS) {
            int rslot = (grp + 3) & 3;
            mbar_expect_tx(mb_base + rslot * 8, 8192);
            bulk_g2s(w_base + rslot * 8192,
                     fc1_w + (long)(i0 + (grp + 3) * 8) * FC1_OUT, 8192,
                     mb_base + rslot * 8);
        }
        const float* wrow = w_s + slot * 2048;
        unsigned long long w01 = pack2(wrow[0 * FC1_OUT + t], wrow[1 * FC1_OUT + t]);
        unsigned long long w23 = pack2(wrow[2 * FC1_OUT + t], wrow[3 * FC1_OUT + t]);
        unsigned long long w45 = pack2(wrow[4 * FC1_OUT + t], wrow[5 * FC1_OUT + t]);
        unsigned long long w67 = pack2(wrow[6 * FC1_OUT + t], wrow[7 * FC1_OUT + t]);
#pragma unroll
        for (int g = 0; g < NG; g++) {
            float4 A0 = a4[g * (CHUNK / 4) + grp * 2];
            float4 A1 = a4[g * (CHUNK / 4) + grp * 2 + 1];
            fma2(r2[g], pack2(A0.x, A0.y), w01);
            fma2(r2[g], pack2(A0.z, A0.w), w23);
            fma2(r2[g], pack2(A1.x, A1.y), w45);
            fma2(r2[g], pack2(A1.z, A1.w), w67);
        }
    }
    float* outp = g_t1p + blockIdx.x * (NG * FC1_OUT);
#pragma unroll
    for (int g = 0; g < NG; g++)
        outp[g * FC1_OUT + t] = unpack_sum(r2[g]);
}

// ==================== kernel 4: tail = reduce partials + fc2 ====================
// grid 16 (one block per graph) x 1024 threads.
__global__ void tail_kernel(const float* __restrict__ fc1_b,
                            const float* __restrict__ fc2_w,
                            const float* __restrict__ fc2_b,
                            float* __restrict__ out) {
    __shared__ float sp[1024];
    __shared__ float s[FC1_OUT];
    int g = blockIdx.x, t = threadIdx.x;
    int o = t & 255, q = t >> 8;                 // q in 0..3: slice of partials

    const float* p = g_t1p + g * FC1_OUT + o;
    float acc = 0.0f;
    const int SLICE = FC1_BLOCKS / 4;            // 128
#pragma unroll 8
    for (int i = 0; i < SLICE; i++)
        acc += p[(q * SLICE + i) * (NG * FC1_OUT)];
    sp[q * 256 + o] = acc;
    __syncthreads();
    if (t < FC1_OUT)
        s[t] = fmaxf(sp[t] + sp[256 + t] + sp[512 + t] + sp[768 + t] + fc1_b[t], 0.0f);
    __syncthreads();

    // fc2: 64 outputs x 16 threads each (16 k per thread), shfl reduce
    int oo = t >> 4, qq = t & 15;
    float a2 = 0.0f;
#pragma unroll
    for (int k = qq * 16; k < qq * 16 + 16; k++)
        a2 = fmaf(s[k], fc2_w[k * FC2_OUT + oo], a2);
    a2 += __shfl_down_sync(~0u, a2, 8, 16);
    a2 += __shfl_down_sync(~0u, a2, 4, 16);
    a2 += __shfl_down_sync(~0u, a2, 2, 16);
    a2 += __shfl_down_sync(~0u, a2, 1, 16);
    if (qq == 0)
        out[g * FC2_OUT + oo] = a2 + fc2_b[oo];
}

extern "C" void kernel_launch(void* const* d_in, const int* in_sizes, int n_in,
                              void* d_out, int out_size) {
    zero_kernel<<<NN / 256, 256>>>();
    build_kernel<<<NB, NT>>>(d_in[1], (const float*)d_in[0], (const float*)d_in[2]);
    agg_all_kernel<<<NBA, NT>>>((const float*)d_in[4], (const float*)d_in[3],
                                (const float*)d_in[6], (const float*)d_in[5],
                                (const float*)d_in[7]);
    fc1_kernel<<<FC1_BLOCKS, 256>>>((const float*)d_in[8]);
    tail_kernel<<<NG, 1024>>>((const float*)d_in[9],
                              (const float*)d_in[10],
                              (const float*)d_in[11],
                              (float*)d_out);
}

// round 15
// speedup vs baseline: 1.0856x; 1.0417x over previous
#include <cuda_runtime.h>
#include <cstdint>

static constexpr int NG      = 16;
static constexpr int NPG     = 4096;
static constexpr int NN      = NG * NPG;     // 65536 nodes
static constexpr int EE      = 1048576;      // edges
static constexpr int H       = 32;           // hidden
static constexpr int FC1_IN  = NPG * H;      // 131072
static constexpr int FC1_OUT = 256;
static constexpr int FC2_OUT = 64;
static constexpr int CHUNK   = 256;          // fc1 rows per block
static constexpr int FC1_BLOCKS = FC1_IN / CHUNK;   // 512
static constexpr int NGROUPS = CHUNK / 8;    // 32 pipeline groups per block
static constexpr int EPAD    = EE + 8 * NN;  // padded CSR capacity

static constexpr int NB = 888;               // persistent grid (build kernel)
static constexpr int NT = 256;
static constexpr int NWARP = NB * 8;

// agg kernel: 5 blocks/SM
static constexpr int NBA = 740;              // 148 x 5
static constexpr int NWARPA = NBA * 8;

// -------- scratch (device globals; no allocation allowed) --------
__device__ int   g_degi[NN];
__device__ int   g_cnt [NN];
__device__ int   g_off [NN];          // block-local exclusive offsets (padded degrees)
__device__ int   g_bsum[256];         // per-256-node-chunk bases (after scan2)
__device__ float g_dinv[NN];
__device__ int   g_eidx[EPAD];        // padded CSR: src indices grouped by dst
__device__ float g_h0 [(NN + 1) * H]; // +1 dummy zero row for CSR padding
__device__ float g_h1 [(NN + 1) * H];
__device__ float g_act[NN * H];       // final pre-activated features for fc1
__device__ float g_t1p[FC1_BLOCKS * NG * FC1_OUT];   // fc1 partials (8 MB)

// -------- software grid barriers (separate for each persistent kernel) ---
__device__ unsigned          g_bar_count;
__device__ volatile unsigned g_bar_gen;
__device__ unsigned          g_bar_count2;
__device__ volatile unsigned g_bar_gen2;

template<int N>
__device__ __forceinline__ void grid_sync_n(unsigned* cnt, volatile unsigned* gen_p) {
    __syncthreads();
    if (threadIdx.x == 0) {
        unsigned gen = *gen_p;
        __threadfence();                      // release
        unsigned old = atomicAdd(cnt, 1u);
        if (old == (unsigned)N - 1u) {
            *cnt = 0u;
            __threadfence();
            *gen_p = gen + 1u;                // release
        } else {
            while (*gen_p == gen) __nanosleep(64);
            __threadfence();                  // acquire
        }
    }
    __syncthreads();
}

// ---- packed f32x2 helpers (sm_103a) ----
__device__ __forceinline__ void fma2(unsigned long long& d,
                                     unsigned long long a,
                                     unsigned long long b) {
    asm("fma.rn.f32x2 %0, %1, %2, %0;" : "+l"(d) : "l"(a), "l"(b));
}
__device__ __forceinline__ unsigned long long pack2(float lo, float hi) {
    unsigned long long r;
    asm("mov.b64 %0, {%1, %2};" : "=l"(r) : "f"(lo), "f"(hi));
    return r;
}
__device__ __forceinline__ float unpack_sum(unsigned long long v) {
    float lo, hi;
    asm("mov.b64 {%0, %1}, %2;" : "=f"(lo), "=f"(hi) : "l"(v));
    return lo + hi;
}

// ---- mbarrier + bulk-copy helpers ----
__device__ __forceinline__ void mbar_init(uint32_t mbar, int count) {
    asm volatile("mbarrier.init.shared.b64 [%0], %1;" :: "r"(mbar), "r"(count) : "memory");
}
__device__ __forceinline__ void mbar_expect_tx(uint32_t mbar, int bytes) {
    asm volatile("mbarrier.arrive.expect_tx.shared.b64 _, [%0], %1;"
                 :: "r"(mbar), "r"(bytes) : "memory");
}
__device__ __forceinline__ void bulk_g2s(uint32_t dst, const void* src,
                                         int bytes, uint32_t mbar) {
    asm volatile("cp.async.bulk.shared::cta.global.mbarrier::complete_tx::bytes "
                 "[%0], [%1], %2, [%3];"
                 :: "r"(dst), "l"(src), "r"(bytes), "r"(mbar) : "memory");
}
__device__ __forceinline__ void mbar_wait(uint32_t mbar, int parity) {
    asm volatile(
        "{\n\t.reg .pred P1;\n\t"
        "WAIT_LOOP_%=:\n\t"
        "mbarrier.try_wait.parity.shared.b64 P1, [%0], %1;\n\t"
        "@P1 bra.uni WAIT_DONE_%=;\n\t"
        "bra.uni WAIT_LOOP_%=;\n\t"
        "WAIT_DONE_%=:\n\t}"
        :: "r"(mbar), "r"(parity) : "memory");
}

// ==================== kernels 0/1: zero counters (agg lands at index 3) ==
__global__ void zero_degi_kernel() {
    g_degi[blockIdx.x * 256 + threadIdx.x] = 0;
}
__global__ void zero_cnt_kernel() {
    g_cnt[blockIdx.x * 256 + threadIdx.x] = 0;
    if (blockIdx.x == 0 && threadIdx.x < 32) {   // dummy zero rows for padding
        g_h0[NN * H + threadIdx.x] = 0.0f;
        g_h1[NN * H + threadIdx.x] = 0.0f;
    }
}

// ==================== kernel 2: build (persistent) ====================
__global__ __launch_bounds__(NT, 6)
void build_kernel(const void* __restrict__ ei,
                  const float* __restrict__ x,
                  const float* __restrict__ W1) {
    __shared__ float sh[16 * 32];
    __shared__ int   shi[8];

    const int t = threadIdx.x, bid = blockIdx.x;
    const int lane = t & 31, wp = t >> 5;

    // dtype detect, per block (int64 buffers: odd 32-bit words all zero)
    const unsigned* w32 = (const unsigned*)ei;
    const int is64 = __syncthreads_and(w32[2 * t + 1] == 0u);

    // ---- P0: degree histogram ----
    if (is64) {
        const long long* p = (const long long*)ei + EE;
        for (int e = bid * NT + t; e < EE; e += NB * NT)
            atomicAdd(&g_degi[(int)__ldcs(&p[e])], 1);
    } else {
        const int* p = (const int*)ei + EE;
        for (int e = bid * NT + t; e < EE; e += NB * NT)
            atomicAdd(&g_degi[__ldcs(&p[e])], 1);
    }
    grid_sync_n<NB>(&g_bar_count, &g_bar_gen);

    // ---- P1: per-256-chunk exclusive scan of PADDED degrees ----
    if (bid < 256) {
        int i = bid * 256 + t;
        int v = g_degi[i];
        g_dinv[i] = rsqrtf((float)v + 1.0f);
        int pv = (v + 7) & ~7;               // pad to multiple of 8
        int s = pv;
#pragma unroll
        for (int off = 1; off < 32; off <<= 1) {
            int xx = __shfl_up_sync(~0u, s, off);
            if (lane >= off) s += xx;
        }
        if (lane == 31) shi[wp] = s;
        __syncthreads();
        if (wp == 0) {
            int orig = (lane < 8) ? shi[lane] : 0;
            int ws = orig;
#pragma unroll
            for (int off = 1; off < 8; off <<= 1) {
                int xx = __shfl_up_sync(~0u, ws, off);
                if (lane >= off) ws += xx;
            }
            if (lane < 8) shi[lane] = ws - orig;
        }
        __syncthreads();
        g_off[i] = s - pv + shi[wp];
        if (t == 255) g_bsum[bid] = s + shi[7];
    }
    grid_sync_n<NB>(&g_bar_count, &g_bar_gen);

    // ---- P2: exclusive scan of 256 chunk totals (block 0) ----
    if (bid == 0) {
        int v = g_bsum[t];
        int s = v;
#pragma unroll
        for (int off = 1; off < 32; off <<= 1) {
            int xx = __shfl_up_sync(~0u, s, off);
            if (lane >= off) s += xx;
        }
        if (lane == 31) shi[wp] = s;
        __syncthreads();
        if (wp == 0) {
            int orig = (lane < 8) ? shi[lane] : 0;
            int ws = orig;
#pragma unroll
            for (int off = 1; off < 8; off <<= 1) {
                int xx = __shfl_up_sync(~0u, ws, off);
                if (lane >= off) ws += xx;
            }
            if (lane < 8) shi[lane] = ws - orig;
        }
        __syncthreads();
        g_bsum[t] = s - v + shi[wp];
    }
    grid_sync_n<NB>(&g_bar_count, &g_bar_gen);

    // ---- P3: CSR fill + padding + layer-1 transform ----
    for (int i = t; i < 16 * 32; i += NT) sh[i] = W1[i];
    __syncthreads();
    if (is64) {
        const long long* p = (const long long*)ei;
        for (int e = bid * NT + t; e < EE; e += NB * NT) {
            int s = (int)__ldcs(&p[e]);
            int d = (int)__ldcs(&p[EE + e]);
            g_eidx[g_off[d] + g_bsum[d >> 8] + atomicAdd(&g_cnt[d], 1)] = s;
        }
    } else {
        const int* p = (const int*)ei;
        for (int e = bid * NT + t; e < EE; e += NB * NT) {
            int s = __ldcs(&p[e]);
            int d = __ldcs(&p[EE + e]);
            g_eidx[g_off[d] + g_bsum[d >> 8] + atomicAdd(&g_cnt[d], 1)] = s;
        }
    }
    // pad slots [off+deg, off+pdeg) -> dummy node NN (zero feature row).
    // Disjoint from real fills; no ordering needed vs the atomic fill above.
    for (int n = bid * NT + t; n < NN; n += NB * NT) {
        int deg  = g_degi[n];
        int pdeg = (deg + 7) & ~7;
        int off  = g_off[n] + g_bsum[n >> 8];
        for (int j = deg; j < pdeg; j++)
            g_eidx[off + j] = NN;
    }
    for (int n = bid * 8 + wp; n < NN; n += NWARP) {
        float a = (lane < 16) ? x[n * 16 + lane] : 0.0f;
        float o = 0.0f;
#pragma unroll
        for (int k = 0; k < 16; k++)
            o = fmaf(__shfl_sync(~0u, a, k), sh[k * 32 + lane], o);
        g_h0[n * 32 + lane] = o * g_dinv[n];
    }
}

// ==================== kernel 3: agg_all (persistent) ====================
// Padded CSR: every row is a multiple of 8, 8-aligned -> the gather loop is
// exactly (int4, int4) index loads + 8 row gathers, no prologue/tail.
template<int LAYER>
__device__ __forceinline__ void agg_phase(const float* __restrict__ W,
                                          const float* __restrict__ b,
                                          float* sh, int bid, int t) {
    const float* hs_in = (LAYER == 1) ? g_h1 : g_h0;
    float* outp = (LAYER == 0) ? g_h1 : (LAYER == 1) ? g_h0 : g_act;
    if (LAYER < 2)
        for (int i = t; i < H * H; i += NT) sh[i] = W[i];
    __syncthreads();
    int lane = t & 31, wp = t >> 5;
    float bl = b[lane];
    const float* hp = hs_in + lane;
    for (int n = bid * 8 + wp; n < NN; n += NWARPA) {
        int start = g_off[n] + g_bsum[n >> 8];
        int end   = start + ((g_degi[n] + 7) & ~7);
        float a0 = hs_in[n * H + lane];   // self-loop term
        float a1 = 0.f, a2 = 0.f, a3 = 0.f;
        float a4 = 0.f, a5 = 0.f, a6 = 0.f, a7 = 0.f;
        for (int e = start; e < end; e += 8) {
            int4 i0 = *reinterpret_cast<const int4*>(&g_eidx[e]);
            int4 i1 = *reinterpret_cast<const int4*>(&g_eidx[e + 4]);
            a0 += hp[i0.x * H]; a1 += hp[i0.y * H];
            a2 += hp[i0.z * H]; a3 += hp[i0.w * H];
            a4 += hp[i1.x * H]; a5 += hp[i1.y * H];
            a6 += hp[i1.z * H]; a7 += hp[i1.w * H];
        }
        float dv = g_dinv[n];
        float agg = ((a0 + a1) + (a2 + a3)) + ((a4 + a5) + (a6 + a7));
        float a = fmaxf(dv * agg + bl, 0.0f);
        if (LAYER == 2) { outp[n * H + lane] = a; continue; }
        float o = 0.0f;
#pragma unroll
        for (int k = 0; k < H; k++)
            o = fmaf(__shfl_sync(~0u, a, k), sh[k * H + lane], o);
        outp[n * H + lane] = o * dv;
    }
}

__global__ __launch_bounds__(NT, 5)
void agg_all_kernel(const float* __restrict__ W2, const float* __restrict__ b1,
                    const float* __restrict__ W3, const float* __restrict__ b2,
                    const float* __restrict__ b3) {
    __shared__ float sh[H * H];
    const int t = threadIdx.x, bid = blockIdx.x;
    agg_phase<0>(W2, b1, sh, bid, t);
    grid_sync_n<NBA>(&g_bar_count2, &g_bar_gen2);
    agg_phase<1>(W3, b2, sh, bid, t);
    grid_sync_n<NBA>(&g_bar_count2, &g_bar_gen2);
    agg_phase<2>(nullptr, b3, sh, bid, t);
}

// ==================== kernel 4: fc1 partials (cp.async.bulk pipelined) ===
__global__ __launch_bounds__(256, 4)
void fc1_kernel(const float* __restrict__ fc1_w) {
    __shared__ __align__(16)  float a_s[NG * CHUNK];           // 16 KB
    __shared__ __align__(128) float w_s[4 * 8 * FC1_OUT];      // 32 KB
    __shared__ __align__(8)   unsigned long long mbar[4];
    int t  = threadIdx.x;                              // output column 0..255
    int i0 = blockIdx.x * CHUNK;

    uint32_t w_base = (uint32_t)__cvta_generic_to_shared(w_s);
    uint32_t mb_base = (uint32_t)__cvta_generic_to_shared(mbar);

    if (t == 0) {
#pragma unroll
        for (int s = 0; s < 4; s++) mbar_init(mb_base + s * 8, 1);
    }
    __syncthreads();

    if (t == 0) {
#pragma unroll
        for (int grp = 0; grp < 3; grp++) {
            mbar_expect_tx(mb_base + grp * 8, 8192);
            bulk_g2s(w_base + grp * 8192,
                     fc1_w + (long)(i0 + grp * 8) * FC1_OUT, 8192,
                     mb_base + grp * 8);
        }
    }

    for (int idx = t; idx < NG * (CHUNK / 4); idx += 256) {
        int g  = idx / (CHUNK / 4);
        int i4 = idx & (CHUNK / 4 - 1);
        float4 v = *reinterpret_cast<const float4*>(g_act + g * FC1_IN + i0 + i4 * 4);
        *reinterpret_cast<float4*>(&a_s[g * CHUNK + i4 * 4]) = v;
    }

    unsigned long long r2[NG];
#pragma unroll
    for (int g = 0; g < NG; g++) r2[g] = 0ull;

    const float4* a4 = reinterpret_cast<const float4*>(a_s);

    for (int grp = 0; grp < NGROUPS; grp++) {
        int slot = grp & 3;
        mbar_wait(mb_base + slot * 8, (grp >> 2) & 1);
        __syncthreads();
        if (t == 0 && grp + 3 < NGROUPS) {
            int rslot = (grp + 3) & 3;
            mbar_expect_tx(mb_base + rslot * 8, 8192);
            bulk_g2s(w_base + rslot * 8192,
                     fc1_w + (long)(i0 + (grp + 3) * 8) * FC1_OUT, 8192,
                     mb_base + rslot * 8);
        }
        const float* wrow = w_s + slot * 2048;
        unsigned long long w01 = pack2(wrow[0 * FC1_OUT + t], wrow[1 * FC1_OUT + t]);
        unsigned long long w23 = pack2(wrow[2 * FC1_OUT + t], wrow[3 * FC1_OUT + t]);
        unsigned long long w45 = pack2(wrow[4 * FC1_OUT + t], wrow[5 * FC1_OUT + t]);
        unsigned long long w67 = pack2(wrow[6 * FC1_OUT + t], wrow[7 * FC1_OUT + t]);
#pragma unroll
        for (int g = 0; g < NG; g++) {
            float4 A0 = a4[g * (CHUNK / 4) + grp * 2];
            float4 A1 = a4[g * (CHUNK / 4) + grp * 2 + 1];
            fma2(r2[g], pack2(A0.x, A0.y), w01);
            fma2(r2[g], pack2(A0.z, A0.w), w23);
            fma2(r2[g], pack2(A1.x, A1.y), w45);
            fma2(r2[g], pack2(A1.z, A1.w), w67);
        }
    }
    float* outp = g_t1p + blockIdx.x * (NG * FC1_OUT);
#pragma unroll
    for (int g = 0; g < NG; g++)
        outp[g * FC1_OUT + t] = unpack_sum(r2[g]);
}

// ==================== kernel 5: tail = reduce partials + fc2 ====================
__global__ void tail_kernel(const float* __restrict__ fc1_b,
                            const float* __restrict__ fc2_w,
                            const float* __restrict__ fc2_b,
                            float* __restrict__ out) {
    __shared__ float sp[1024];
    __shared__ float s[FC1_OUT];
    int g = blockIdx.x, t = threadIdx.x;
    int o = t & 255, q = t >> 8;                 // q in 0..3: slice of partials

    const float* p = g_t1p + g * FC1_OUT + o;
    float acc = 0.0f;
    const int SLICE = FC1_BLOCKS / 4;            // 128
#pragma unroll 8
    for (int i = 0; i < SLICE; i++)
        acc += p[(q * SLICE + i) * (NG * FC1_OUT)];
    sp[q * 256 + o] = acc;
    __syncthreads();
    if (t < FC1_OUT)
        s[t] = fmaxf(sp[t] + sp[256 + t] + sp[512 + t] + sp[768 + t] + fc1_b[t], 0.0f);
    __syncthreads();

    int oo = t >> 4, qq = t & 15;
    float a2 = 0.0f;
#pragma unroll
    for (int k = qq * 16; k < qq * 16 + 16; k++)
        a2 = fmaf(s[k], fc2_w[k * FC2_OUT + oo], a2);
    a2 += __shfl_down_sync(~0u, a2, 8, 16);
    a2 += __shfl_down_sync(~0u, a2, 4, 16);
    a2 += __shfl_down_sync(~0u, a2, 2, 16);
    a2 += __shfl_down_sync(~0u, a2, 1, 16);
    if (qq == 0)
        out[g * FC2_OUT + oo] = a2 + fc2_b[oo];
}

extern "C" void kernel_launch(void* const* d_in, const int* in_sizes, int n_in,
                              void* d_out, int out_size) {
    zero_degi_kernel<<<NN / 256, 256>>>();
    zero_cnt_kernel<<<NN / 256, 256>>>();
    build_kernel<<<NB, NT>>>(d_in[1], (const float*)d_in[0], (const float*)d_in[2]);
    agg_all_kernel<<<NBA, NT>>>((const float*)d_in[4], (const float*)d_in[3],
                                (const float*)d_in[6], (const float*)d_in[5],
                                (const float*)d_in[7]);
    fc1_kernel<<<FC1_BLOCKS, 256>>>((const float*)d_in[8]);
    tail_kernel<<<NG, 1024>>>((const float*)d_in[9],
                              (const float*)d_in[10],
                              (const float*)d_in[11],
                              (float*)d_out);
}